// round 8
// baseline (speedup 1.0000x reference)
#include <cuda_runtime.h>
#include <math.h>

// GraphQNN: 22-qubit real-amplitude state-vector simulation.
// R8: latency-hiding round.
//  - 1024 threads x 16 elems (8 f32x2 pairs): 64 warps/SM (2 CTAs) vs ~28.
//  - coefficients + parity masks in __constant__ (filled via capturable D2D
//    cudaMemcpyToSymbolAsync from __device__ staging): no coef shfls, no
//    coef registers -> p[8]=16 state regs fits the 32-reg budget.
// Sweep structure (5 sweeps) unchanged:
//   K1 passL : init product state + stage1 low RYs
//   K2 passHH: stage1 hi RYs -> sign -> stage2 hi RYs
//   K3 passL : stage2 low RYs
//   K4 passH1: sign at load -> stage3 hi RYs
//   K5 passL : stage3 low RYs + fused expvals

#define NQ 22
#define DIM (1 << NQ)
#define LOWB 14
#define LOWDIM (1 << LOWB)
#define FULL 0xffffffffu
typedef unsigned long long ull;

__device__ float g_state[DIM];
__device__ float g_ccs[4][NQ];     // staging, written by k_setup
__device__ float g_sss[4][NQ];
__device__ unsigned g_pms[NQ];

__constant__ float c_c[4][NQ];     // [stage][bitpos]
__constant__ float c_s[4][NQ];
__constant__ unsigned c_pm[NQ];    // per bit position: mask of paired positions

__device__ __forceinline__ unsigned par(unsigned v) {
    return (unsigned)__popc(v) & 1u;
}

// ---------------------------------------------------------------- f32x2
__device__ __forceinline__ ull pk2(float x, float y) {
    ull r; asm("mov.b64 %0, {%1,%2};" : "=l"(r) : "f"(x), "f"(y)); return r;
}
__device__ __forceinline__ float2 upk2(ull v) {
    float2 f; asm("mov.b64 {%0,%1}, %2;" : "=f"(f.x), "=f"(f.y) : "l"(v)); return f;
}
__device__ __forceinline__ ull mul2_(ull a, ull b) {
    ull r; asm("mul.rn.f32x2 %0, %1, %2;" : "=l"(r) : "l"(a), "l"(b)); return r;
}
__device__ __forceinline__ ull fma2_(ull a, ull b, ull c) {
    ull r; asm("fma.rn.f32x2 %0, %1, %2, %3;" : "=l"(r) : "l"(a), "l"(b), "l"(c)); return r;
}

// butterfly on 16 elements held as 8 pairs.
// BIT = 0: pair-internal (scalar). BIT>=1: packed across pair-index bit BIT-1.
template <int BIT>
__device__ __forceinline__ void bfly8(ull* p, float c, float s) {
    if (BIT == 0) {
#pragma unroll
        for (int i = 0; i < 8; i++) {
            float2 v = upk2(p[i]);
            p[i] = pk2(fmaf(c, v.x, -(s * v.y)), fmaf(s, v.x, c * v.y));
        }
    } else {
        const ull cc = pk2(c, c), ss = pk2(s, s), ns = pk2(-s, -s);
#pragma unroll
        for (int i0 = 0; i0 < 8; i0++) {
            if ((i0 & (1 << (BIT - 1))) == 0) {
                int i1 = i0 | (1 << (BIT - 1));
                ull v0 = p[i0], v1 = p[i1];
                p[i0] = fma2_(cc, v0, mul2_(ns, v1));
                p[i1] = fma2_(ss, v0, mul2_(cc, v1));
            }
        }
    }
}

// ---------------------------------------------------------------- setup
__global__ void k_setup(const float* __restrict__ feat,
                        const float* __restrict__ adj,
                        const float* __restrict__ params,
                        float* __restrict__ out) {
    int t = threadIdx.x;
    if (t < 4 * NQ) {
        int s = t / NQ;
        int b = t % NQ;
        int q = NQ - 1 - b;
        float th = (s == 0 ? feat[q] : params[(s - 1) * NQ + q]) * 0.5f;
        g_ccs[s][b] = cosf(th);
        g_sss[s][b] = sinf(th);
    }
    if (t < NQ) {
        int q = NQ - 1 - t;
        unsigned m = 0;
        for (int qq = 0; qq < NQ; qq++) {
            if (qq == q) continue;
            int i = q < qq ? q : qq;
            int j = q < qq ? qq : q;
            if (adj[i * NQ + j] > 0.0f) m |= (1u << (NQ - 1 - qq));
        }
        g_pms[t] = m;
        out[t] = 0.0f;
    }
}

__device__ __forceinline__ unsigned signB(unsigned ulow) {
    unsigned Bb = 0;
#pragma unroll
    for (int a = 1; a < LOWB; a++)
        Bb ^= ((ulow >> a) & 1u) & par(ulow & c_pm[a] & ((1u << a) - 1u));
    return Bb;
}
__device__ __forceinline__ unsigned signCL(unsigned ulow) {
    unsigned cl = 0;
#pragma unroll
    for (int j = 0; j < 8; j++)
        cl |= par(ulow & c_pm[14 + j] & 0x3FFFu) << j;
    return cl;
}

// ---------------------------------------------------------------- K2 passHH
// bits 14..21, two layers fused. Tile 256 h x 64 low. 1024 thr x 16 elems.
// View A: k = h0-3 (global 14-17), hv = h4-7; pairs along h0.
// View B: k = h4-7 (global 18-21), hv = h0-3; pairs along h4.
// Exchange: u = (h<<6)|tl, scalar (banks = lane, conflict-free).
template <int S1, int S2>
__global__ void __launch_bounds__(1024, 2) k_passHH() {
    extern __shared__ float sm[];   // 16384 floats
    const int t = threadIdx.x;
    const int lane = t & 31;
    const int tl = t & 63;
    const unsigned hv = t >> 6;          // 4 bits
    const int low = (blockIdx.x << 6) + tl;
    const unsigned ulow = (unsigned)low;

    // ---- sign constants (VIEW B): k = global 18-21, hv = global 14-17
    unsigned Bb = signB(ulow);
    unsigned cl = signCL(ulow);
    unsigned Ahv = 0;
#pragma unroll
    for (int a = 1; a < 4; a++)
        Ahv ^= ((hv >> a) & 1u) & par(hv & ((c_pm[14 + a] >> 14) & ((1u << a) - 1u)));
    unsigned cm = 0;
#pragma unroll
    for (int i = 0; i < 4; i++)
        cm |= par(hv & ((c_pm[18 + i] >> 14) & 15u)) << i;
    const unsigned km = ((cl >> 4) & 15u) ^ cm;
    const unsigned cbase = Bb ^ par(hv & (cl & 15u)) ^ Ahv;
    unsigned ab = 0;
#pragma unroll
    for (int i = 1; i < 4; i++)
        ab ^= (((unsigned)lane >> i) & 1u) &
              par((unsigned)lane & ((c_pm[18 + i] >> 18) & ((1u << i) - 1u)));
    const unsigned akk = __ballot_sync(FULL, ab);

    ull p[8];
    // ---- view A load: h = (hv<<4)|k, pairs along h0
#pragma unroll
    for (int j = 0; j < 8; j++)
        p[j] = pk2(g_state[(((hv << 4) | (2 * j)) << LOWB) | low],
                   g_state[(((hv << 4) | (2 * j + 1)) << LOWB) | low]);

    // stage S1 global bits 14-17
    bfly8<0>(p, c_c[S1][14], c_s[S1][14]);
    bfly8<1>(p, c_c[S1][15], c_s[S1][15]);
    bfly8<2>(p, c_c[S1][16], c_s[S1][16]);
    bfly8<3>(p, c_c[S1][17], c_s[S1][17]);

    // exchange A -> B
#pragma unroll
    for (int j = 0; j < 8; j++) {
        float2 v = upk2(p[j]);
        sm[(((hv << 4) | (2 * j)) << 6) | tl] = v.x;
        sm[(((hv << 4) | (2 * j + 1)) << 6) | tl] = v.y;
    }
    __syncthreads();
#pragma unroll
    for (int i = 0; i < 8; i++)
        p[i] = pk2(sm[((2 * i) << 10) | (hv << 6) | tl],
                   sm[((2 * i + 1) << 10) | (hv << 6) | tl]);

    // stage S1 global bits 18-21
    bfly8<0>(p, c_c[S1][18], c_s[S1][18]);
    bfly8<1>(p, c_c[S1][19], c_s[S1][19]);
    bfly8<2>(p, c_c[S1][20], c_s[S1][20]);
    bfly8<3>(p, c_c[S1][21], c_s[S1][21]);

    // ---- diagonal sign (k = 2i lo, 2i+1 hi)
#pragma unroll
    for (int i = 0; i < 8; i++) {
        unsigned lo = cbase ^ ((akk >> (2 * i)) & 1u) ^ par((unsigned)(2 * i) & km);
        unsigned hi = cbase ^ ((akk >> (2 * i + 1)) & 1u) ^ par((unsigned)(2 * i + 1) & km);
        p[i] ^= ((ull)hi << 63) | ((ull)lo << 31);
    }

    // stage S2 global bits 18-21
    bfly8<0>(p, c_c[S2][18], c_s[S2][18]);
    bfly8<1>(p, c_c[S2][19], c_s[S2][19]);
    bfly8<2>(p, c_c[S2][20], c_s[S2][20]);
    bfly8<3>(p, c_c[S2][21], c_s[S2][21]);

    // exchange B -> A (in-place: per-thread write set == read set)
#pragma unroll
    for (int i = 0; i < 8; i++) {
        float2 v = upk2(p[i]);
        sm[((2 * i) << 10) | (hv << 6) | tl] = v.x;
        sm[((2 * i + 1) << 10) | (hv << 6) | tl] = v.y;
    }
    __syncthreads();
#pragma unroll
    for (int j = 0; j < 8; j++)
        p[j] = pk2(sm[(((hv << 4) | (2 * j)) << 6) | tl],
                   sm[(((hv << 4) | (2 * j + 1)) << 6) | tl]);

    // stage S2 global bits 14-17
    bfly8<0>(p, c_c[S2][14], c_s[S2][14]);
    bfly8<1>(p, c_c[S2][15], c_s[S2][15]);
    bfly8<2>(p, c_c[S2][16], c_s[S2][16]);
    bfly8<3>(p, c_c[S2][17], c_s[S2][17]);

#pragma unroll
    for (int j = 0; j < 8; j++) {
        float2 v = upk2(p[j]);
        g_state[(((hv << 4) | (2 * j)) << LOWB) | low] = v.x;
        g_state[(((hv << 4) | (2 * j + 1)) << LOWB) | low] = v.y;
    }
}

// ---------------------------------------------------------------- K4 passH1
// sign at load (view A: k = global 14-17, hv = global 18-21) + stage S hi RYs.
template <int S>
__global__ void __launch_bounds__(1024, 2) k_passH1() {
    extern __shared__ float sm[];
    const int t = threadIdx.x;
    const int lane = t & 31;
    const int tl = t & 63;
    const unsigned hv = t >> 6;          // h4-7 = global 18-21 (view A)
    const int low = (blockIdx.x << 6) + tl;
    const unsigned ulow = (unsigned)low;

    // ---- sign constants (VIEW A)
    unsigned Bb = signB(ulow);
    unsigned cl = signCL(ulow);
    unsigned chm = 0;
#pragma unroll
    for (int a = 0; a < 4; a++)
        chm |= par(hv & ((c_pm[14 + a] >> 18) & 15u)) << a;
    unsigned Ahh = 0;
#pragma unroll
    for (int a = 1; a < 4; a++)
        Ahh ^= ((hv >> a) & 1u) & par(hv & ((c_pm[18 + a] >> 18) & ((1u << a) - 1u)));
    unsigned ab = 0;
#pragma unroll
    for (int a = 1; a < 4; a++)
        ab ^= (((unsigned)lane >> a) & 1u) &
              par((unsigned)lane & ((c_pm[14 + a] >> 14) & ((1u << a) - 1u)));
    const unsigned akk = __ballot_sync(FULL, ab);
    const unsigned km = (cl & 15u) ^ chm;
    const unsigned cbase = Bb ^ par(hv & ((cl >> 4) & 15u)) ^ Ahh;

    ull p[8];
#pragma unroll
    for (int j = 0; j < 8; j++)
        p[j] = pk2(g_state[(((hv << 4) | (2 * j)) << LOWB) | low],
                   g_state[(((hv << 4) | (2 * j + 1)) << LOWB) | low]);
#pragma unroll
    for (int j = 0; j < 8; j++) {
        unsigned lo = cbase ^ ((akk >> (2 * j)) & 1u) ^ par((unsigned)(2 * j) & km);
        unsigned hi = cbase ^ ((akk >> (2 * j + 1)) & 1u) ^ par((unsigned)(2 * j + 1) & km);
        p[j] ^= ((ull)hi << 63) | ((ull)lo << 31);
    }

    // stage S global bits 14-17
    bfly8<0>(p, c_c[S][14], c_s[S][14]);
    bfly8<1>(p, c_c[S][15], c_s[S][15]);
    bfly8<2>(p, c_c[S][16], c_s[S][16]);
    bfly8<3>(p, c_c[S][17], c_s[S][17]);

    // exchange A -> B
#pragma unroll
    for (int j = 0; j < 8; j++) {
        float2 v = upk2(p[j]);
        sm[(((hv << 4) | (2 * j)) << 6) | tl] = v.x;
        sm[(((hv << 4) | (2 * j + 1)) << 6) | tl] = v.y;
    }
    __syncthreads();
#pragma unroll
    for (int i = 0; i < 8; i++)
        p[i] = pk2(sm[((2 * i) << 10) | (hv << 6) | tl],
                   sm[((2 * i + 1) << 10) | (hv << 6) | tl]);

    // stage S global bits 18-21
    bfly8<0>(p, c_c[S][18], c_s[S][18]);
    bfly8<1>(p, c_c[S][19], c_s[S][19]);
    bfly8<2>(p, c_c[S][20], c_s[S][20]);
    bfly8<3>(p, c_c[S][21], c_s[S][21]);

    // store from view B: h = (k<<4)|hv
#pragma unroll
    for (int i = 0; i < 8; i++) {
        float2 v = upk2(p[i]);
        g_state[((((2 * i) << 4) | hv) << LOWB) | low] = v.x;
        g_state[((((2 * i + 1) << 4) | hv) << LOWB) | low] = v.y;
    }
}

// ---------------------------------------------------------------- pass L
// bits 0..13 within a contiguous 16384 block. 1024 thr x 16 elems.
// Views: A{k=x0-3, int x0} B{k=x4-7, int x4} C{k=x8-11, int x8} D{k=x10-13,
// pair x10, packed x12-13}. Natural layout + pair-preserving swizzle.
__device__ __forceinline__ int lw(int x) { return x ^ (((x >> 5) & 15) << 1); }

template <int STAGE, bool INIT, bool LAST>
__global__ void __launch_bounds__(1024, 2) k_passL(float* __restrict__ out) {
    extern __shared__ float sm[];
    __shared__ float acc[NQ];
    const int t = threadIdx.x;           // 10 bits
    const int lane = t & 31;
    const int base = blockIdx.x << LOWB;
    ull p[8];

    if (LAST && t < NQ) acc[t] = 0.0f;

    if (INIT) {
        // product state: x = (t<<4)|k; bits 0-3 = k, 4-13 = t, 14-21 = blk
        float a = 1.0f;
        const unsigned blk = blockIdx.x;
#pragma unroll
        for (int b = 0; b < 8; b++)
            a *= ((blk >> b) & 1) ? c_s[0][14 + b] : c_c[0][14 + b];
#pragma unroll
        for (int b = 0; b < 10; b++)
            a *= ((t >> b) & 1) ? c_s[0][4 + b] : c_c[0][4 + b];
#pragma unroll
        for (int j = 0; j < 8; j++) {    // j = x1-3
            float aj = a;
#pragma unroll
            for (int b = 0; b < 3; b++)
                aj *= ((j >> b) & 1) ? c_s[0][1 + b] : c_c[0][1 + b];
            p[j] = pk2(aj * c_c[0][0], aj * c_s[0][0]);
        }
    } else {
        const float4* gp = reinterpret_cast<const float4*>(&g_state[base + t * 16]);
#pragma unroll
        for (int i = 0; i < 4; i++) {
            float4 q = gp[i];
            p[2 * i] = pk2(q.x, q.y);
            p[2 * i + 1] = pk2(q.z, q.w);
        }
    }

    // ---- A: int x0; packed x1-3
    bfly8<0>(p, c_c[STAGE][0], c_s[STAGE][0]);
    bfly8<1>(p, c_c[STAGE][1], c_s[STAGE][1]);
    bfly8<2>(p, c_c[STAGE][2], c_s[STAGE][2]);
    bfly8<3>(p, c_c[STAGE][3], c_s[STAGE][3]);

    // A store: STS.64, pairs along x0
#pragma unroll
    for (int j = 0; j < 8; j++)
        *reinterpret_cast<ull*>(&sm[lw((t << 4) | (2 * j))]) = p[j];
    __syncthreads();

    // ---- B: k = x4-7 (int x4, packed x5-7); fixed x0-3 = t&15, x8-13 = t>>4
    {
        const int xb = (t & 15) | ((t >> 4) << 8);
#pragma unroll
        for (int i = 0; i < 8; i++)
            p[i] = pk2(sm[lw(xb | ((2 * i) << 4))],
                       sm[lw(xb | ((2 * i + 1) << 4))]);

        bfly8<0>(p, c_c[STAGE][4], c_s[STAGE][4]);
        bfly8<1>(p, c_c[STAGE][5], c_s[STAGE][5]);
        bfly8<2>(p, c_c[STAGE][6], c_s[STAGE][6]);
        bfly8<3>(p, c_c[STAGE][7], c_s[STAGE][7]);

#pragma unroll
        for (int i = 0; i < 8; i++) {
            float2 v = upk2(p[i]);
            sm[lw(xb | ((2 * i) << 4))] = v.x;
            sm[lw(xb | ((2 * i + 1) << 4))] = v.y;
        }
    }
    __syncthreads();

    // ---- C: k = x8-11 (int x8, packed x9-11); fixed x0-7 = t&255, x12-13 = t>>8
    {
        const int xc = (t & 255) | ((t >> 8) << 12);
#pragma unroll
        for (int i = 0; i < 8; i++)
            p[i] = pk2(sm[lw(xc | ((2 * i) << 8))],
                       sm[lw(xc | ((2 * i + 1) << 8))]);

        bfly8<0>(p, c_c[STAGE][8],  c_s[STAGE][8]);
        bfly8<1>(p, c_c[STAGE][9],  c_s[STAGE][9]);
        bfly8<2>(p, c_c[STAGE][10], c_s[STAGE][10]);
        bfly8<3>(p, c_c[STAGE][11], c_s[STAGE][11]);

#pragma unroll
        for (int i = 0; i < 8; i++) {
            float2 v = upk2(p[i]);
            sm[lw(xc | ((2 * i) << 8))] = v.x;
            sm[lw(xc | ((2 * i + 1) << 8))] = v.y;
        }
    }
    __syncthreads();

    // ---- D: k = x10-13, pair x10, i = x11-13; bfly x12 (i bit1), x13 (i bit2)
#pragma unroll
    for (int i = 0; i < 8; i++)
        p[i] = pk2(sm[lw(t | ((2 * i) << 10))],
                   sm[lw(t | ((2 * i + 1) << 10))]);

    bfly8<2>(p, c_c[STAGE][12], c_s[STAGE][12]);
    bfly8<3>(p, c_c[STAGE][13], c_s[STAGE][13]);

    if (!LAST) {
#pragma unroll
        for (int i = 0; i < 8; i++) {
            float2 v = upk2(p[i]);
            g_state[base | ((2 * i) << 10) | t] = v.x;
            g_state[base | ((2 * i + 1) << 10) | t] = v.y;
        }
    } else {
        // fused expvals. x bits: 0-4 lane, 5-9 warp, 10 pair, 11-13 i, 14-21 blk
        float P = 0.f, S0 = 0.f, S1 = 0.f, S2 = 0.f, S3 = 0.f;
#pragma unroll
        for (int i = 0; i < 8; i++) {
            float2 v = upk2(p[i]);
            float px = v.x * v.x, py = v.y * v.y;
            float pp = px + py;
            P += pp;
            S0 += px - py;                 // bit 10
            S1 += (i & 1) ? -pp : pp;      // bit 11
            S2 += (i & 2) ? -pp : pp;      // bit 12
            S3 += (i & 4) ? -pp : pp;      // bit 13
        }
        float R0 = (lane & 1)  ? -P : P;   // bit 0
        float R1 = (lane & 2)  ? -P : P;   // bit 1
        float R2 = (lane & 4)  ? -P : P;   // bit 2
        float R3 = (lane & 8)  ? -P : P;   // bit 3
        float R4 = (lane & 16) ? -P : P;   // bit 4
#pragma unroll
        for (int o = 16; o; o >>= 1) {
            P  += __shfl_xor_sync(FULL, P, o);
            S0 += __shfl_xor_sync(FULL, S0, o);
            S1 += __shfl_xor_sync(FULL, S1, o);
            S2 += __shfl_xor_sync(FULL, S2, o);
            S3 += __shfl_xor_sync(FULL, S3, o);
            R0 += __shfl_xor_sync(FULL, R0, o);
            R1 += __shfl_xor_sync(FULL, R1, o);
            R2 += __shfl_xor_sync(FULL, R2, o);
            R3 += __shfl_xor_sync(FULL, R3, o);
            R4 += __shfl_xor_sync(FULL, R4, o);
        }
        if (lane == 0) {
            int wrp = t >> 5;              // bits 5-9 (5 bits, 32 warps)
            atomicAdd(&acc[0], R0);
            atomicAdd(&acc[1], R1);
            atomicAdd(&acc[2], R2);
            atomicAdd(&acc[3], R3);
            atomicAdd(&acc[4], R4);
#pragma unroll
            for (int b = 5; b < 10; b++)
                atomicAdd(&acc[b], ((wrp >> (b - 5)) & 1) ? -P : P);
            atomicAdd(&acc[10], S0);
            atomicAdd(&acc[11], S1);
            atomicAdd(&acc[12], S2);
            atomicAdd(&acc[13], S3);
#pragma unroll
            for (int b = 14; b < NQ; b++)
                atomicAdd(&acc[b], ((blockIdx.x >> (b - 14)) & 1) ? -P : P);
        }
        __syncthreads();
        if (t < NQ) atomicAdd(&out[NQ - 1 - t], acc[t]);
    }
}

// ---------------------------------------------------------------- launch
extern "C" void kernel_launch(void* const* d_in, const int* in_sizes, int n_in,
                              void* d_out, int out_size) {
    const float* feat = (const float*)d_in[0];
    const float* adj = (const float*)d_in[1];
    const float* params = (const float*)d_in[2];
    float* out = (float*)d_out;

    const int SMEM = LOWDIM * (int)sizeof(float);   // 65536
    cudaFuncSetAttribute(k_passL<1, true,  false>, cudaFuncAttributeMaxDynamicSharedMemorySize, SMEM);
    cudaFuncSetAttribute(k_passHH<1, 2>,           cudaFuncAttributeMaxDynamicSharedMemorySize, SMEM);
    cudaFuncSetAttribute(k_passL<2, false, false>, cudaFuncAttributeMaxDynamicSharedMemorySize, SMEM);
    cudaFuncSetAttribute(k_passH1<3>,              cudaFuncAttributeMaxDynamicSharedMemorySize, SMEM);
    cudaFuncSetAttribute(k_passL<3, false, true>,  cudaFuncAttributeMaxDynamicSharedMemorySize, SMEM);

    k_setup<<<1, 128>>>(feat, adj, params, out);

    // stage coefficients into __constant__ (D2D, graph-capturable)
    void *pc = nullptr, *ps = nullptr, *pm = nullptr;
    cudaGetSymbolAddress(&pc, g_ccs);
    cudaGetSymbolAddress(&ps, g_sss);
    cudaGetSymbolAddress(&pm, g_pms);
    cudaMemcpyToSymbolAsync(c_c, pc, sizeof(float) * 4 * NQ, 0, cudaMemcpyDeviceToDevice);
    cudaMemcpyToSymbolAsync(c_s, ps, sizeof(float) * 4 * NQ, 0, cudaMemcpyDeviceToDevice);
    cudaMemcpyToSymbolAsync(c_pm, pm, sizeof(unsigned) * NQ, 0, cudaMemcpyDeviceToDevice);

    k_passL<1, true,  false><<<DIM / LOWDIM, 1024, SMEM>>>(out);
    k_passHH<1, 2>          <<<LOWDIM / 64, 1024, SMEM>>>();
    k_passL<2, false, false><<<DIM / LOWDIM, 1024, SMEM>>>(out);
    k_passH1<3>             <<<LOWDIM / 64, 1024, SMEM>>>();
    k_passL<3, false, true> <<<DIM / LOWDIM, 1024, SMEM>>>(out);
}

// round 9
// speedup vs baseline: 1.1479x; 1.1479x over previous
#include <cuda_runtime.h>
#include <math.h>

// GraphQNN: 22-qubit real-amplitude state-vector simulation.
// R9: consolidation. 512 thr x 32 elems (R6 structure, best measured),
// R7's passL (64-bit B view, fastest passL), R6's H kernels (fastest H),
// and coefficients/parity masks in __constant__ (from R8: kills the coef
// shfl stream + register pressure; sign masks become uniform LDC).
// Sweeps: K1 passL(init+st1 low) K2 passHH(st1 hi, sign, st2 hi)
//         K3 passL(st2 low) K4 passH1(sign, st3 hi) K5 passL(st3 low+expvals)

#define NQ 22
#define DIM (1 << NQ)
#define LOWB 14
#define LOWDIM (1 << LOWB)
#define FULL 0xffffffffu
typedef unsigned long long ull;

__device__ float g_state[DIM];
__device__ float g_ccs[4][NQ];     // staging, written by k_setup
__device__ float g_sss[4][NQ];
__device__ unsigned g_pms[NQ];

__constant__ float c_c[4][NQ];     // [stage][bitpos]
__constant__ float c_s[4][NQ];
__constant__ unsigned c_pm[NQ];

__device__ __forceinline__ unsigned par(unsigned v) {
    return (unsigned)__popc(v) & 1u;
}

// ---------------------------------------------------------------- f32x2
__device__ __forceinline__ ull pk2(float x, float y) {
    ull r; asm("mov.b64 %0, {%1,%2};" : "=l"(r) : "f"(x), "f"(y)); return r;
}
__device__ __forceinline__ float2 upk2(ull v) {
    float2 f; asm("mov.b64 {%0,%1}, %2;" : "=f"(f.x), "=f"(f.y) : "l"(v)); return f;
}
__device__ __forceinline__ ull mul2_(ull a, ull b) {
    ull r; asm("mul.rn.f32x2 %0, %1, %2;" : "=l"(r) : "l"(a), "l"(b)); return r;
}
__device__ __forceinline__ ull fma2_(ull a, ull b, ull c) {
    ull r; asm("fma.rn.f32x2 %0, %1, %2, %3;" : "=l"(r) : "l"(a), "l"(b), "l"(c)); return r;
}

// butterfly on 32 elements held as 16 pairs p[i] = (elem 2i, elem 2i+1).
// BIT = 0: pair-internal (scalar). BIT>=1: packed across pair-index bit BIT-1.
template <int BIT>
__device__ __forceinline__ void bflyp(ull* p, float c, float s) {
    if (BIT == 0) {
#pragma unroll
        for (int i = 0; i < 16; i++) {
            float2 v = upk2(p[i]);
            p[i] = pk2(fmaf(c, v.x, -(s * v.y)), fmaf(s, v.x, c * v.y));
        }
    } else {
        const ull cc = pk2(c, c), ss = pk2(s, s), ns = pk2(-s, -s);
#pragma unroll
        for (int i0 = 0; i0 < 16; i0++) {
            if ((i0 & (1 << (BIT - 1))) == 0) {
                int i1 = i0 | (1 << (BIT - 1));
                ull v0 = p[i0], v1 = p[i1];
                p[i0] = fma2_(cc, v0, mul2_(ns, v1));
                p[i1] = fma2_(ss, v0, mul2_(cc, v1));
            }
        }
    }
}

// ---------------------------------------------------------------- setup
__global__ void k_setup(const float* __restrict__ feat,
                        const float* __restrict__ adj,
                        const float* __restrict__ params,
                        float* __restrict__ out) {
    int t = threadIdx.x;
    if (t < 4 * NQ) {
        int s = t / NQ;
        int b = t % NQ;
        int q = NQ - 1 - b;
        float th = (s == 0 ? feat[q] : params[(s - 1) * NQ + q]) * 0.5f;
        g_ccs[s][b] = cosf(th);
        g_sss[s][b] = sinf(th);
    }
    if (t < NQ) {
        int q = NQ - 1 - t;
        unsigned m = 0;
        for (int qq = 0; qq < NQ; qq++) {
            if (qq == q) continue;
            int i = q < qq ? q : qq;
            int j = q < qq ? qq : q;
            if (adj[i * NQ + j] > 0.0f) m |= (1u << (NQ - 1 - qq));
        }
        g_pms[t] = m;
        out[t] = 0.0f;
    }
}

__device__ __forceinline__ unsigned signB(unsigned ulow) {
    unsigned Bb = 0;
#pragma unroll
    for (int a = 1; a < LOWB; a++)
        Bb ^= ((ulow >> a) & 1u) & par(ulow & c_pm[a] & ((1u << a) - 1u));
    return Bb;
}
__device__ __forceinline__ unsigned signCL(unsigned ulow) {
    unsigned cl = 0;
#pragma unroll
    for (int j = 0; j < 8; j++)
        cl |= par(ulow & c_pm[14 + j] & 0x3FFFu) << j;
    return cl;
}

// ---------------------------------------------------------------- K2 passHH
// bits 14..21, two layers fused. Tile 256 h x 64 low. 512 thr x 32.
// View A: regs k = h0-4 (global 14-18), hv = h5-7.
// View B: regs k = h3-7 (global 17-21), hv = h0-2.  (R6 scalar exchange)
template <int S1, int S2>
__global__ void __launch_bounds__(512, 2) k_passHH() {
    extern __shared__ float sm[];   // 16384 floats
    const int t = threadIdx.x;
    const int lane = t & 31;
    const int tl = t & 63;
    const unsigned hv = t >> 6;          // hhi in view A, hlo in view B
    const int low = (blockIdx.x << 6) + tl;
    const unsigned ulow = (unsigned)low;

    // ---- sign constants (VIEW B): h = hv | (k<<3) after exchange
    unsigned Bb = signB(ulow);
    unsigned cl = signCL(ulow);
    unsigned Alo = 0;
#pragma unroll
    for (int a = 1; a < 3; a++)
        Alo ^= ((hv >> a) & 1u) & par(hv & ((c_pm[14 + a] >> 14) & ((1u << a) - 1u)));
    unsigned cm = 0;
#pragma unroll
    for (int i = 0; i < 5; i++)
        cm |= par(hv & ((c_pm[17 + i] >> 14) & 7u)) << i;
    const unsigned km = ((cl >> 3) & 31u) ^ cm;
    const unsigned cbase = Bb ^ par(hv & (cl & 7u)) ^ Alo;
    unsigned ab = 0;
#pragma unroll
    for (int i = 1; i < 5; i++)
        ab ^= (((unsigned)lane >> i) & 1u) &
              par((unsigned)lane & ((c_pm[17 + i] >> 17) & ((1u << i) - 1u)));
    const unsigned akk = __ballot_sync(FULL, ab);

    ull p[16];
    // ---- view A load (natural layout), pairs along h0
#pragma unroll
    for (int i = 0; i < 16; i++)
        p[i] = pk2(g_state[(((hv << 5) | (2 * i)) << LOWB) | low],
                   g_state[(((hv << 5) | (2 * i + 1)) << LOWB) | low]);

    // stage S1 global bits 14-18 (view A k bits 0-4)
    bflyp<0>(p, c_c[S1][14], c_s[S1][14]);
    bflyp<1>(p, c_c[S1][15], c_s[S1][15]);
    bflyp<2>(p, c_c[S1][16], c_s[S1][16]);
    bflyp<3>(p, c_c[S1][17], c_s[S1][17]);
    bflyp<4>(p, c_c[S1][18], c_s[S1][18]);

    // exchange A -> B (scalar, [h][tl], conflict-free)
#pragma unroll
    for (int i = 0; i < 16; i++) {
        float2 v = upk2(p[i]);
        sm[(((hv << 5) | (2 * i)) << 6) | tl] = v.x;
        sm[(((hv << 5) | (2 * i + 1)) << 6) | tl] = v.y;
    }
    __syncthreads();
#pragma unroll
    for (int i = 0; i < 16; i++)
        p[i] = pk2(sm[((((2 * i) << 3) | hv) << 6) | tl],
                   sm[((((2 * i + 1) << 3) | hv) << 6) | tl]);

    // stage S1 global bits 19-21 (view B k bits 2-4)
    bflyp<2>(p, c_c[S1][19], c_s[S1][19]);
    bflyp<3>(p, c_c[S1][20], c_s[S1][20]);
    bflyp<4>(p, c_c[S1][21], c_s[S1][21]);

    // ---- diagonal sign (k = 2i lo, 2i+1 hi)
#pragma unroll
    for (int i = 0; i < 16; i++) {
        unsigned lo = cbase ^ ((akk >> (2 * i)) & 1u) ^ par((unsigned)(2 * i) & km);
        unsigned hi = cbase ^ ((akk >> (2 * i + 1)) & 1u) ^ par((unsigned)(2 * i + 1) & km);
        p[i] ^= ((ull)hi << 63) | ((ull)lo << 31);
    }

    // stage S2 global bits 19-21
    bflyp<2>(p, c_c[S2][19], c_s[S2][19]);
    bflyp<3>(p, c_c[S2][20], c_s[S2][20]);
    bflyp<4>(p, c_c[S2][21], c_s[S2][21]);

    // exchange B -> A (in-place: write set == read set)
#pragma unroll
    for (int i = 0; i < 16; i++) {
        float2 v = upk2(p[i]);
        sm[((((2 * i) << 3) | hv) << 6) | tl] = v.x;
        sm[((((2 * i + 1) << 3) | hv) << 6) | tl] = v.y;
    }
    __syncthreads();
#pragma unroll
    for (int i = 0; i < 16; i++)
        p[i] = pk2(sm[(((hv << 5) | (2 * i)) << 6) | tl],
                   sm[(((hv << 5) | (2 * i + 1)) << 6) | tl]);

    // stage S2 global bits 14-18
    bflyp<0>(p, c_c[S2][14], c_s[S2][14]);
    bflyp<1>(p, c_c[S2][15], c_s[S2][15]);
    bflyp<2>(p, c_c[S2][16], c_s[S2][16]);
    bflyp<3>(p, c_c[S2][17], c_s[S2][17]);
    bflyp<4>(p, c_c[S2][18], c_s[S2][18]);

#pragma unroll
    for (int i = 0; i < 16; i++) {
        float2 v = upk2(p[i]);
        g_state[(((hv << 5) | (2 * i)) << LOWB) | low] = v.x;
        g_state[(((hv << 5) | (2 * i + 1)) << LOWB) | low] = v.y;
    }
}

// ---------------------------------------------------------------- K4 passH1
// sign at load (view A: h = (hv<<5)|k, k bits = global 14-18) + stage S hi RYs.
template <int S>
__global__ void __launch_bounds__(512, 2) k_passH1() {
    extern __shared__ float sm[];
    const int t = threadIdx.x;
    const int lane = t & 31;
    const int tl = t & 63;
    const unsigned hv = t >> 6;          // h5-7
    const int low = (blockIdx.x << 6) + tl;
    const unsigned ulow = (unsigned)low;

    // ---- sign constants (VIEW A)
    unsigned Bb = signB(ulow);
    unsigned cl = signCL(ulow);
    unsigned chm = 0;
#pragma unroll
    for (int a = 0; a < 5; a++)
        chm |= par(hv & ((c_pm[14 + a] >> 19) & 7u)) << a;
    unsigned Ahh = 0;
#pragma unroll
    for (int a = 1; a < 3; a++)
        Ahh ^= ((hv >> a) & 1u) & par(hv & ((c_pm[19 + a] >> 19) & ((1u << a) - 1u)));
    unsigned ab = 0;
#pragma unroll
    for (int a = 1; a < 5; a++)
        ab ^= (((unsigned)lane >> a) & 1u) &
              par((unsigned)lane & ((c_pm[14 + a] >> 14) & ((1u << a) - 1u)));
    const unsigned akk = __ballot_sync(FULL, ab);
    const unsigned km = (cl & 31u) ^ chm;
    const unsigned cbase = Bb ^ par(hv & (cl >> 5)) ^ Ahh;

    ull p[16];
#pragma unroll
    for (int i = 0; i < 16; i++)
        p[i] = pk2(g_state[(((hv << 5) | (2 * i)) << LOWB) | low],
                   g_state[(((hv << 5) | (2 * i + 1)) << LOWB) | low]);
#pragma unroll
    for (int i = 0; i < 16; i++) {
        unsigned lo = cbase ^ ((akk >> (2 * i)) & 1u) ^ par((unsigned)(2 * i) & km);
        unsigned hi = cbase ^ ((akk >> (2 * i + 1)) & 1u) ^ par((unsigned)(2 * i + 1) & km);
        p[i] ^= ((ull)hi << 63) | ((ull)lo << 31);
    }

    // stage S global bits 14-18
    bflyp<0>(p, c_c[S][14], c_s[S][14]);
    bflyp<1>(p, c_c[S][15], c_s[S][15]);
    bflyp<2>(p, c_c[S][16], c_s[S][16]);
    bflyp<3>(p, c_c[S][17], c_s[S][17]);
    bflyp<4>(p, c_c[S][18], c_s[S][18]);

    // exchange A -> B (scalar)
#pragma unroll
    for (int i = 0; i < 16; i++) {
        float2 v = upk2(p[i]);
        sm[(((hv << 5) | (2 * i)) << 6) | tl] = v.x;
        sm[(((hv << 5) | (2 * i + 1)) << 6) | tl] = v.y;
    }
    __syncthreads();
#pragma unroll
    for (int i = 0; i < 16; i++)
        p[i] = pk2(sm[((((2 * i) << 3) | hv) << 6) | tl],
                   sm[((((2 * i + 1) << 3) | hv) << 6) | tl]);

    // stage S global bits 19-21 (view B k bits 2-4)
    bflyp<2>(p, c_c[S][19], c_s[S][19]);
    bflyp<3>(p, c_c[S][20], c_s[S][20]);
    bflyp<4>(p, c_c[S][21], c_s[S][21]);

    // store from view B: h = (k<<3)|hv
#pragma unroll
    for (int i = 0; i < 16; i++) {
        float2 v = upk2(p[i]);
        g_state[((((2 * i) << 3) | hv) << LOWB) | low] = v.x;
        g_state[((((2 * i + 1) << 3) | hv) << LOWB) | low] = v.y;
    }
}

// ---------------------------------------------------------------- pass L
// R7 structure: views A{0-4, pair=x4} B{x4,5-8: 64-bit} C{9-13, pair=x9}.
// Layout y = x4 | (x0-3)<<1 | (x5-13)<<5, swizzle bits1-4 ^= bits5-8.
__device__ __forceinline__ int lw2(int y) { return y ^ (((y >> 5) & 15) << 1); }

template <int STAGE, bool INIT, bool LAST>
__global__ void __launch_bounds__(512, 2) k_passL(float* __restrict__ out) {
    extern __shared__ float sm[];
    __shared__ float acc[NQ];
    const int t = threadIdx.x;
    const int lane = t & 31;
    const int base = blockIdx.x << LOWB;
    ull p[16];

    if (LAST && t < NQ) acc[t] = 0.0f;

    if (INIT) {
        float a = 1.0f;
        const unsigned blk = blockIdx.x;     // bits 14-21
#pragma unroll
        for (int b = 0; b < 8; b++)
            a *= ((blk >> b) & 1) ? c_s[0][14 + b] : c_c[0][14 + b];
#pragma unroll
        for (int b = 0; b < 9; b++)          // bits 5-13 = t
            a *= ((t >> b) & 1) ? c_s[0][5 + b] : c_c[0][5 + b];
        // pairs along x4: p[j] = (bits0-3 = j, x4 = 0/1)
#pragma unroll
        for (int j = 0; j < 16; j++) {
            float aj = a;
#pragma unroll
            for (int b = 0; b < 4; b++)
                aj *= ((j >> b) & 1) ? c_s[0][b] : c_c[0][b];
            p[j] = pk2(aj * c_c[0][4], aj * c_s[0][4]);
        }
    } else {
        // x = (t<<5)|m; pairs (m, m|16) along x4
        float v[32];
        const float4* gp = reinterpret_cast<const float4*>(&g_state[base + t * 32]);
#pragma unroll
        for (int i = 0; i < 8; i++) {
            float4 q = gp[i];
            v[4 * i] = q.x; v[4 * i + 1] = q.y;
            v[4 * i + 2] = q.z; v[4 * i + 3] = q.w;
        }
#pragma unroll
        for (int j = 0; j < 16; j++)
            p[j] = pk2(v[j], v[j | 16]);
    }

    // ---- A: internal x4; packed x0-3
    bflyp<0>(p, c_c[STAGE][4], c_s[STAGE][4]);
    bflyp<1>(p, c_c[STAGE][0], c_s[STAGE][0]);
    bflyp<2>(p, c_c[STAGE][1], c_s[STAGE][1]);
    bflyp<3>(p, c_c[STAGE][2], c_s[STAGE][2]);
    bflyp<4>(p, c_c[STAGE][3], c_s[STAGE][3]);

    // A store: y = (j<<1) | (t<<5)   (STS.64)
#pragma unroll
    for (int j = 0; j < 16; j++)
        *reinterpret_cast<ull*>(&sm[lw2((j << 1) | (t << 5))]) = p[j];
    __syncthreads();

    // ---- B: internal x4 (retired); packed x5-8 = i. Fixed x0-3 = t&15, x9-13 = t>>4.
    {
        const int yb = ((t & 15) << 1) | ((t >> 4) << 9);
#pragma unroll
        for (int i = 0; i < 16; i++)
            p[i] = *reinterpret_cast<const ull*>(&sm[lw2(yb | (i << 5))]);

        bflyp<1>(p, c_c[STAGE][5], c_s[STAGE][5]);
        bflyp<2>(p, c_c[STAGE][6], c_s[STAGE][6]);
        bflyp<3>(p, c_c[STAGE][7], c_s[STAGE][7]);
        bflyp<4>(p, c_c[STAGE][8], c_s[STAGE][8]);

#pragma unroll
        for (int i = 0; i < 16; i++)
            *reinterpret_cast<ull*>(&sm[lw2(yb | (i << 5))]) = p[i];
    }
    __syncthreads();

    // ---- C: internal x9; packed x10-13 = i. Fixed x0-8 = t.
    const int yc = ((t >> 4) & 1) | ((t & 15) << 1) | (((t >> 5) & 15) << 5);
#pragma unroll
    for (int i = 0; i < 16; i++)
        p[i] = pk2(sm[lw2(yc | ((2 * i) << 9))],
                   sm[lw2(yc | ((2 * i + 1) << 9))]);

    bflyp<0>(p, c_c[STAGE][9],  c_s[STAGE][9]);
    bflyp<1>(p, c_c[STAGE][10], c_s[STAGE][10]);
    bflyp<2>(p, c_c[STAGE][11], c_s[STAGE][11]);
    bflyp<3>(p, c_c[STAGE][12], c_s[STAGE][12]);
    bflyp<4>(p, c_c[STAGE][13], c_s[STAGE][13]);

    if (!LAST) {
#pragma unroll
        for (int i = 0; i < 16; i++) {
            float2 v = upk2(p[i]);
            g_state[base | ((2 * i) << 9) | t] = v.x;
            g_state[base | ((2 * i + 1) << 9) | t] = v.y;
        }
    } else {
        // fused expvals. x bits: 0-4 lane, 5-8 warp, 9 pair, 10-13 i, 14-21 blk.
        float P = 0.f, S0 = 0.f, S1 = 0.f, S2 = 0.f, S3 = 0.f, S4 = 0.f;
#pragma unroll
        for (int i = 0; i < 16; i++) {
            float2 v = upk2(p[i]);
            float px = v.x * v.x, py = v.y * v.y;
            float pp = px + py;
            P += pp;
            S0 += px - py;                 // bit 9
            S1 += (i & 1) ? -pp : pp;      // bit 10
            S2 += (i & 2) ? -pp : pp;      // bit 11
            S3 += (i & 4) ? -pp : pp;      // bit 12
            S4 += (i & 8) ? -pp : pp;      // bit 13
        }
        float R0 = (lane & 1)  ? -P : P;
        float R1 = (lane & 2)  ? -P : P;
        float R2 = (lane & 4)  ? -P : P;
        float R3 = (lane & 8)  ? -P : P;
        float R4 = (lane & 16) ? -P : P;
#pragma unroll
        for (int o = 16; o; o >>= 1) {
            P  += __shfl_xor_sync(FULL, P, o);
            S0 += __shfl_xor_sync(FULL, S0, o);
            S1 += __shfl_xor_sync(FULL, S1, o);
            S2 += __shfl_xor_sync(FULL, S2, o);
            S3 += __shfl_xor_sync(FULL, S3, o);
            S4 += __shfl_xor_sync(FULL, S4, o);
            R0 += __shfl_xor_sync(FULL, R0, o);
            R1 += __shfl_xor_sync(FULL, R1, o);
            R2 += __shfl_xor_sync(FULL, R2, o);
            R3 += __shfl_xor_sync(FULL, R3, o);
            R4 += __shfl_xor_sync(FULL, R4, o);
        }
        if (lane == 0) {
            int wrp = t >> 5;              // bits 5-8
            atomicAdd(&acc[0], R0);
            atomicAdd(&acc[1], R1);
            atomicAdd(&acc[2], R2);
            atomicAdd(&acc[3], R3);
            atomicAdd(&acc[4], R4);
#pragma unroll
            for (int b = 5; b < 9; b++)
                atomicAdd(&acc[b], ((wrp >> (b - 5)) & 1) ? -P : P);
            atomicAdd(&acc[9],  S0);
            atomicAdd(&acc[10], S1);
            atomicAdd(&acc[11], S2);
            atomicAdd(&acc[12], S3);
            atomicAdd(&acc[13], S4);
#pragma unroll
            for (int b = 14; b < NQ; b++)
                atomicAdd(&acc[b], ((blockIdx.x >> (b - 14)) & 1) ? -P : P);
        }
        __syncthreads();
        if (t < NQ) atomicAdd(&out[NQ - 1 - t], acc[t]);
    }
}

// ---------------------------------------------------------------- launch
extern "C" void kernel_launch(void* const* d_in, const int* in_sizes, int n_in,
                              void* d_out, int out_size) {
    const float* feat = (const float*)d_in[0];
    const float* adj = (const float*)d_in[1];
    const float* params = (const float*)d_in[2];
    float* out = (float*)d_out;

    const int SMEM = LOWDIM * (int)sizeof(float);   // 65536
    cudaFuncSetAttribute(k_passL<1, true,  false>, cudaFuncAttributeMaxDynamicSharedMemorySize, SMEM);
    cudaFuncSetAttribute(k_passHH<1, 2>,           cudaFuncAttributeMaxDynamicSharedMemorySize, SMEM);
    cudaFuncSetAttribute(k_passL<2, false, false>, cudaFuncAttributeMaxDynamicSharedMemorySize, SMEM);
    cudaFuncSetAttribute(k_passH1<3>,              cudaFuncAttributeMaxDynamicSharedMemorySize, SMEM);
    cudaFuncSetAttribute(k_passL<3, false, true>,  cudaFuncAttributeMaxDynamicSharedMemorySize, SMEM);

    k_setup<<<1, 128>>>(feat, adj, params, out);

    // stage coefficients into __constant__ (D2D, graph-capturable)
    void *pc = nullptr, *ps = nullptr, *pm = nullptr;
    cudaGetSymbolAddress(&pc, g_ccs);
    cudaGetSymbolAddress(&ps, g_sss);
    cudaGetSymbolAddress(&pm, g_pms);
    cudaMemcpyToSymbolAsync(c_c, pc, sizeof(float) * 4 * NQ, 0, cudaMemcpyDeviceToDevice);
    cudaMemcpyToSymbolAsync(c_s, ps, sizeof(float) * 4 * NQ, 0, cudaMemcpyDeviceToDevice);
    cudaMemcpyToSymbolAsync(c_pm, pm, sizeof(unsigned) * NQ, 0, cudaMemcpyDeviceToDevice);

    k_passL<1, true,  false><<<DIM / LOWDIM, 512, SMEM>>>(out);
    k_passHH<1, 2>          <<<LOWDIM / 64, 512, SMEM>>>();
    k_passL<2, false, false><<<DIM / LOWDIM, 512, SMEM>>>(out);
    k_passH1<3>             <<<LOWDIM / 64, 512, SMEM>>>();
    k_passL<3, false, true> <<<DIM / LOWDIM, 512, SMEM>>>(out);
}

// round 10
// speedup vs baseline: 1.1894x; 1.0361x over previous
#include <cuda_runtime.h>
#include <math.h>

// GraphQNN: 22-qubit real-amplitude state-vector simulation.
// R10: 4 sweeps. The diagonal sign is computable in the L view too (L block
// fixes bits 14-21, so cross terms collapse to per-block GF(2) constants):
//   S1 passL1: init product state + stage1 low RYs
//   S2 passHH: stage1 hi RYs -> sign1 -> stage2 hi RYs
//   S3 passLL: stage2 low RYs -> sign2 -> stage3 low RYs   (one sweep!)
//   S4 passHE: stage3 hi RYs -> fused expvals (no sign, no store)
// L2 traffic 128->96 MB, 5->4 kernels. Everything else = R9 (512thr x 32elem,
// f32x2 butterflies, __constant__ coefficients).

#define NQ 22
#define DIM (1 << NQ)
#define LOWB 14
#define LOWDIM (1 << LOWB)
#define FULL 0xffffffffu
typedef unsigned long long ull;

__device__ float g_state[DIM];
__device__ float g_ccs[4][NQ];     // staging, written by k_setup
__device__ float g_sss[4][NQ];
__device__ unsigned g_pms[NQ];

__constant__ float c_c[4][NQ];     // [stage][bitpos]
__constant__ float c_s[4][NQ];
__constant__ unsigned c_pm[NQ];

__device__ __forceinline__ unsigned par(unsigned v) {
    return (unsigned)__popc(v) & 1u;
}

// ---------------------------------------------------------------- f32x2
__device__ __forceinline__ ull pk2(float x, float y) {
    ull r; asm("mov.b64 %0, {%1,%2};" : "=l"(r) : "f"(x), "f"(y)); return r;
}
__device__ __forceinline__ float2 upk2(ull v) {
    float2 f; asm("mov.b64 {%0,%1}, %2;" : "=f"(f.x), "=f"(f.y) : "l"(v)); return f;
}
__device__ __forceinline__ ull mul2_(ull a, ull b) {
    ull r; asm("mul.rn.f32x2 %0, %1, %2;" : "=l"(r) : "l"(a), "l"(b)); return r;
}
__device__ __forceinline__ ull fma2_(ull a, ull b, ull c) {
    ull r; asm("fma.rn.f32x2 %0, %1, %2, %3;" : "=l"(r) : "l"(a), "l"(b), "l"(c)); return r;
}

// butterfly on 32 elements held as 16 pairs p[i] = (elem 2i, elem 2i+1).
// BIT = 0: pair-internal (scalar). BIT>=1: packed across pair-index bit BIT-1.
template <int BIT>
__device__ __forceinline__ void bflyp(ull* p, float c, float s) {
    if (BIT == 0) {
#pragma unroll
        for (int i = 0; i < 16; i++) {
            float2 v = upk2(p[i]);
            p[i] = pk2(fmaf(c, v.x, -(s * v.y)), fmaf(s, v.x, c * v.y));
        }
    } else {
        const ull cc = pk2(c, c), ss = pk2(s, s), ns = pk2(-s, -s);
#pragma unroll
        for (int i0 = 0; i0 < 16; i0++) {
            if ((i0 & (1 << (BIT - 1))) == 0) {
                int i1 = i0 | (1 << (BIT - 1));
                ull v0 = p[i0], v1 = p[i1];
                p[i0] = fma2_(cc, v0, mul2_(ns, v1));
                p[i1] = fma2_(ss, v0, mul2_(cc, v1));
            }
        }
    }
}

// ---------------------------------------------------------------- setup
__global__ void k_setup(const float* __restrict__ feat,
                        const float* __restrict__ adj,
                        const float* __restrict__ params,
                        float* __restrict__ out) {
    int t = threadIdx.x;
    if (t < 4 * NQ) {
        int s = t / NQ;
        int b = t % NQ;
        int q = NQ - 1 - b;
        float th = (s == 0 ? feat[q] : params[(s - 1) * NQ + q]) * 0.5f;
        g_ccs[s][b] = cosf(th);
        g_sss[s][b] = sinf(th);
    }
    if (t < NQ) {
        int q = NQ - 1 - t;
        unsigned m = 0;
        for (int qq = 0; qq < NQ; qq++) {
            if (qq == q) continue;
            int i = q < qq ? q : qq;
            int j = q < qq ? qq : q;
            if (adj[i * NQ + j] > 0.0f) m |= (1u << (NQ - 1 - qq));
        }
        g_pms[t] = m;
        out[t] = 0.0f;
    }
}

__device__ __forceinline__ unsigned signB(unsigned ulow) {
    unsigned Bb = 0;
#pragma unroll
    for (int a = 1; a < LOWB; a++)
        Bb ^= ((ulow >> a) & 1u) & par(ulow & c_pm[a] & ((1u << a) - 1u));
    return Bb;
}
__device__ __forceinline__ unsigned signCL(unsigned ulow) {
    unsigned cl = 0;
#pragma unroll
    for (int j = 0; j < 8; j++)
        cl |= par(ulow & c_pm[14 + j] & 0x3FFFu) << j;
    return cl;
}

// ---------------------------------------------------------------- S2 passHH
// bits 14..21, two layers fused + sign1. Tile 256 h x 64 low. 512 thr x 32.
// View A: regs k = h0-4 (global 14-18), hv = h5-7.
// View B: regs k = h3-7 (global 17-21), hv = h0-2.
template <int S1, int S2>
__global__ void __launch_bounds__(512, 2) k_passHH() {
    extern __shared__ float sm[];   // 16384 floats
    const int t = threadIdx.x;
    const int lane = t & 31;
    const int tl = t & 63;
    const unsigned hv = t >> 6;          // hhi in view A, hlo in view B
    const int low = (blockIdx.x << 6) + tl;
    const unsigned ulow = (unsigned)low;

    // ---- sign constants (VIEW B): h = hv | (k<<3) after exchange
    unsigned Bb = signB(ulow);
    unsigned cl = signCL(ulow);
    unsigned Alo = 0;
#pragma unroll
    for (int a = 1; a < 3; a++)
        Alo ^= ((hv >> a) & 1u) & par(hv & ((c_pm[14 + a] >> 14) & ((1u << a) - 1u)));
    unsigned cm = 0;
#pragma unroll
    for (int i = 0; i < 5; i++)
        cm |= par(hv & ((c_pm[17 + i] >> 14) & 7u)) << i;
    const unsigned km = ((cl >> 3) & 31u) ^ cm;
    const unsigned cbase = Bb ^ par(hv & (cl & 7u)) ^ Alo;
    unsigned ab = 0;
#pragma unroll
    for (int i = 1; i < 5; i++)
        ab ^= (((unsigned)lane >> i) & 1u) &
              par((unsigned)lane & ((c_pm[17 + i] >> 17) & ((1u << i) - 1u)));
    const unsigned akk = __ballot_sync(FULL, ab);

    ull p[16];
#pragma unroll
    for (int i = 0; i < 16; i++)
        p[i] = pk2(g_state[(((hv << 5) | (2 * i)) << LOWB) | low],
                   g_state[(((hv << 5) | (2 * i + 1)) << LOWB) | low]);

    // stage S1 global bits 14-18 (view A k bits 0-4)
    bflyp<0>(p, c_c[S1][14], c_s[S1][14]);
    bflyp<1>(p, c_c[S1][15], c_s[S1][15]);
    bflyp<2>(p, c_c[S1][16], c_s[S1][16]);
    bflyp<3>(p, c_c[S1][17], c_s[S1][17]);
    bflyp<4>(p, c_c[S1][18], c_s[S1][18]);

    // exchange A -> B (scalar, [h][tl], conflict-free)
#pragma unroll
    for (int i = 0; i < 16; i++) {
        float2 v = upk2(p[i]);
        sm[(((hv << 5) | (2 * i)) << 6) | tl] = v.x;
        sm[(((hv << 5) | (2 * i + 1)) << 6) | tl] = v.y;
    }
    __syncthreads();
#pragma unroll
    for (int i = 0; i < 16; i++)
        p[i] = pk2(sm[((((2 * i) << 3) | hv) << 6) | tl],
                   sm[((((2 * i + 1) << 3) | hv) << 6) | tl]);

    // stage S1 global bits 19-21 (view B k bits 2-4)
    bflyp<2>(p, c_c[S1][19], c_s[S1][19]);
    bflyp<3>(p, c_c[S1][20], c_s[S1][20]);
    bflyp<4>(p, c_c[S1][21], c_s[S1][21]);

    // ---- diagonal sign (k = 2i lo, 2i+1 hi)
#pragma unroll
    for (int i = 0; i < 16; i++) {
        unsigned lo = cbase ^ ((akk >> (2 * i)) & 1u) ^ par((unsigned)(2 * i) & km);
        unsigned hi = cbase ^ ((akk >> (2 * i + 1)) & 1u) ^ par((unsigned)(2 * i + 1) & km);
        p[i] ^= ((ull)hi << 63) | ((ull)lo << 31);
    }

    // stage S2 global bits 19-21
    bflyp<2>(p, c_c[S2][19], c_s[S2][19]);
    bflyp<3>(p, c_c[S2][20], c_s[S2][20]);
    bflyp<4>(p, c_c[S2][21], c_s[S2][21]);

    // exchange B -> A (in-place: write set == read set)
#pragma unroll
    for (int i = 0; i < 16; i++) {
        float2 v = upk2(p[i]);
        sm[((((2 * i) << 3) | hv) << 6) | tl] = v.x;
        sm[((((2 * i + 1) << 3) | hv) << 6) | tl] = v.y;
    }
    __syncthreads();
#pragma unroll
    for (int i = 0; i < 16; i++)
        p[i] = pk2(sm[(((hv << 5) | (2 * i)) << 6) | tl],
                   sm[(((hv << 5) | (2 * i + 1)) << 6) | tl]);

    // stage S2 global bits 14-18
    bflyp<0>(p, c_c[S2][14], c_s[S2][14]);
    bflyp<1>(p, c_c[S2][15], c_s[S2][15]);
    bflyp<2>(p, c_c[S2][16], c_s[S2][16]);
    bflyp<3>(p, c_c[S2][17], c_s[S2][17]);
    bflyp<4>(p, c_c[S2][18], c_s[S2][18]);

#pragma unroll
    for (int i = 0; i < 16; i++) {
        float2 v = upk2(p[i]);
        g_state[(((hv << 5) | (2 * i)) << LOWB) | low] = v.x;
        g_state[(((hv << 5) | (2 * i + 1)) << LOWB) | low] = v.y;
    }
}

// ---------------------------------------------------------------- S4 passHE
// stage S hi RYs + fused expvals. No sign (applied in S3), no store.
// View A: k = global 14-18 (pair 14), hv = global 19-21.
// View B: k = global 17-21 (pair 17), hv = global 14-16.
template <int S>
__global__ void __launch_bounds__(512, 2) k_passHE(float* __restrict__ out) {
    extern __shared__ float sm[];
    __shared__ float acc[NQ];
    const int t = threadIdx.x;
    const int lane = t & 31;
    const int tl = t & 63;
    const unsigned hv = t >> 6;          // h5-7 in view A
    const int low = (blockIdx.x << 6) + tl;

    if (t < NQ) acc[t] = 0.0f;

    ull p[16];
#pragma unroll
    for (int i = 0; i < 16; i++)
        p[i] = pk2(g_state[(((hv << 5) | (2 * i)) << LOWB) | low],
                   g_state[(((hv << 5) | (2 * i + 1)) << LOWB) | low]);

    // stage S global bits 14-18
    bflyp<0>(p, c_c[S][14], c_s[S][14]);
    bflyp<1>(p, c_c[S][15], c_s[S][15]);
    bflyp<2>(p, c_c[S][16], c_s[S][16]);
    bflyp<3>(p, c_c[S][17], c_s[S][17]);
    bflyp<4>(p, c_c[S][18], c_s[S][18]);

    // exchange A -> B (scalar)
#pragma unroll
    for (int i = 0; i < 16; i++) {
        float2 v = upk2(p[i]);
        sm[(((hv << 5) | (2 * i)) << 6) | tl] = v.x;
        sm[(((hv << 5) | (2 * i + 1)) << 6) | tl] = v.y;
    }
    __syncthreads();
#pragma unroll
    for (int i = 0; i < 16; i++)
        p[i] = pk2(sm[((((2 * i) << 3) | hv) << 6) | tl],
                   sm[((((2 * i + 1) << 3) | hv) << 6) | tl]);

    // stage S global bits 19-21 (view B k bits 2-4)
    bflyp<2>(p, c_c[S][19], c_s[S][19]);
    bflyp<3>(p, c_c[S][20], c_s[S][20]);
    bflyp<4>(p, c_c[S][21], c_s[S][21]);

    // ---- fused expvals, view B element bits:
    // 0-5 = tl (0-4 lane, 5 = warp bit0), 6-13 = blk, 14-16 = hv (warp bits
    // 1-3), 17 = pair, 18-21 = i.
    float P = 0.f, S17 = 0.f, S18 = 0.f, S19 = 0.f, S20 = 0.f, S21 = 0.f;
#pragma unroll
    for (int i = 0; i < 16; i++) {
        float2 v = upk2(p[i]);
        float px = v.x * v.x, py = v.y * v.y;
        float pp = px + py;
        P += pp;
        S17 += px - py;
        S18 += (i & 1) ? -pp : pp;
        S19 += (i & 2) ? -pp : pp;
        S20 += (i & 4) ? -pp : pp;
        S21 += (i & 8) ? -pp : pp;
    }
    float R0 = (lane & 1)  ? -P : P;
    float R1 = (lane & 2)  ? -P : P;
    float R2 = (lane & 4)  ? -P : P;
    float R3 = (lane & 8)  ? -P : P;
    float R4 = (lane & 16) ? -P : P;
#pragma unroll
    for (int o = 16; o; o >>= 1) {
        P   += __shfl_xor_sync(FULL, P, o);
        S17 += __shfl_xor_sync(FULL, S17, o);
        S18 += __shfl_xor_sync(FULL, S18, o);
        S19 += __shfl_xor_sync(FULL, S19, o);
        S20 += __shfl_xor_sync(FULL, S20, o);
        S21 += __shfl_xor_sync(FULL, S21, o);
        R0  += __shfl_xor_sync(FULL, R0, o);
        R1  += __shfl_xor_sync(FULL, R1, o);
        R2  += __shfl_xor_sync(FULL, R2, o);
        R3  += __shfl_xor_sync(FULL, R3, o);
        R4  += __shfl_xor_sync(FULL, R4, o);
    }
    if (lane == 0) {
        unsigned w = (unsigned)(t >> 5);     // bit0 -> global 5, bits1-3 -> 14-16
        atomicAdd(&acc[0], R0);
        atomicAdd(&acc[1], R1);
        atomicAdd(&acc[2], R2);
        atomicAdd(&acc[3], R3);
        atomicAdd(&acc[4], R4);
        atomicAdd(&acc[5], (w & 1u) ? -P : P);
#pragma unroll
        for (int b = 6; b < 14; b++)
            atomicAdd(&acc[b], ((blockIdx.x >> (b - 6)) & 1) ? -P : P);
#pragma unroll
        for (int b = 14; b < 17; b++)
            atomicAdd(&acc[b], ((w >> (b - 13)) & 1u) ? -P : P);
        atomicAdd(&acc[17], S17);
        atomicAdd(&acc[18], S18);
        atomicAdd(&acc[19], S19);
        atomicAdd(&acc[20], S20);
        atomicAdd(&acc[21], S21);
    }
    __syncthreads();
    if (t < NQ) atomicAdd(&out[NQ - 1 - t], acc[t]);
}

// ---------------------------------------------------------------- L-view
// Layout y = x4 | (x0-3)<<1 | (x5-13)<<5, swizzle bits1-4 ^= bits5-8.
__device__ __forceinline__ int lw2(int y) { return y ^ (((y >> 5) & 15) << 1); }

// ---------------------------------------------------------------- S1 passL1
// init product state + stage-1 low RYs (views A,B,C), scalar store.
__global__ void __launch_bounds__(512, 2) k_passL1() {
    extern __shared__ float sm[];
    const int t = threadIdx.x;
    const int base = blockIdx.x << LOWB;
    ull p[16];

    // product state: x bits 5-13 = t, 14-21 = blk, pairs along x4
    float a = 1.0f;
    const unsigned blk = blockIdx.x;
#pragma unroll
    for (int b = 0; b < 8; b++)
        a *= ((blk >> b) & 1) ? c_s[0][14 + b] : c_c[0][14 + b];
#pragma unroll
    for (int b = 0; b < 9; b++)
        a *= ((t >> b) & 1) ? c_s[0][5 + b] : c_c[0][5 + b];
#pragma unroll
    for (int j = 0; j < 16; j++) {
        float aj = a;
#pragma unroll
        for (int b = 0; b < 4; b++)
            aj *= ((j >> b) & 1) ? c_s[0][b] : c_c[0][b];
        p[j] = pk2(aj * c_c[0][4], aj * c_s[0][4]);
    }

    // A: internal x4; packed x0-3 (stage 1)
    bflyp<0>(p, c_c[1][4], c_s[1][4]);
    bflyp<1>(p, c_c[1][0], c_s[1][0]);
    bflyp<2>(p, c_c[1][1], c_s[1][1]);
    bflyp<3>(p, c_c[1][2], c_s[1][2]);
    bflyp<4>(p, c_c[1][3], c_s[1][3]);

#pragma unroll
    for (int j = 0; j < 16; j++)
        *reinterpret_cast<ull*>(&sm[lw2((j << 1) | (t << 5))]) = p[j];
    __syncthreads();

    // B: packed x5-8
    {
        const int yb = ((t & 15) << 1) | ((t >> 4) << 9);
#pragma unroll
        for (int i = 0; i < 16; i++)
            p[i] = *reinterpret_cast<const ull*>(&sm[lw2(yb | (i << 5))]);

        bflyp<1>(p, c_c[1][5], c_s[1][5]);
        bflyp<2>(p, c_c[1][6], c_s[1][6]);
        bflyp<3>(p, c_c[1][7], c_s[1][7]);
        bflyp<4>(p, c_c[1][8], c_s[1][8]);

#pragma unroll
        for (int i = 0; i < 16; i++)
            *reinterpret_cast<ull*>(&sm[lw2(yb | (i << 5))]) = p[i];
    }
    __syncthreads();

    // C: internal x9; packed x10-13
    const int yc = ((t >> 4) & 1) | ((t & 15) << 1) | (((t >> 5) & 15) << 5);
#pragma unroll
    for (int i = 0; i < 16; i++)
        p[i] = pk2(sm[lw2(yc | ((2 * i) << 9))],
                   sm[lw2(yc | ((2 * i + 1) << 9))]);

    bflyp<0>(p, c_c[1][9],  c_s[1][9]);
    bflyp<1>(p, c_c[1][10], c_s[1][10]);
    bflyp<2>(p, c_c[1][11], c_s[1][11]);
    bflyp<3>(p, c_c[1][12], c_s[1][12]);
    bflyp<4>(p, c_c[1][13], c_s[1][13]);

#pragma unroll
    for (int i = 0; i < 16; i++) {
        float2 v = upk2(p[i]);
        g_state[base | ((2 * i) << 9) | t] = v.x;
        g_state[base | ((2 * i + 1) << 9) | t] = v.y;
    }
}

// ---------------------------------------------------------------- S3 passLL
// stage SA low RYs -> sign (in C view) -> stage SB low RYs, one sweep.
// Views: A(x4 int, x0-3 packed) -> B(x5-8) -> C(x9 int, x10-13) -> B' -> A'.
template <int SA, int SB>
__global__ void __launch_bounds__(512, 2) k_passLL() {
    extern __shared__ float sm[];
    const int t = threadIdx.x;           // 9 bits = x5-13 (A view), x0-8 (C view)
    const int lane = t & 31;
    const int base = blockIdx.x << LOWB;
    const unsigned blk = blockIdx.x;
    ull p[16];

    // ---- load (natural, float4), pairs along x4: x = (t<<5)|m, p[j]=(m=j, m=j|16)
    {
        float v[32];
        const float4* gp = reinterpret_cast<const float4*>(&g_state[base + t * 32]);
#pragma unroll
        for (int i = 0; i < 8; i++) {
            float4 q = gp[i];
            v[4 * i] = q.x; v[4 * i + 1] = q.y;
            v[4 * i + 2] = q.z; v[4 * i + 3] = q.w;
        }
#pragma unroll
        for (int j = 0; j < 16; j++)
            p[j] = pk2(v[j], v[j | 16]);
    }

    // ---- sign constants for the C view (x0-8 = t, x9 = pair, x10-13 = i)
    // parity(x) = B(t) ^ cross(t,blk) ^ A(blk) ^ x9-terms ^ i-terms
    unsigned Mblk = 0;                               // XOR of low-masks of set blk bits
#pragma unroll
    for (int j = 0; j < 8; j++)
        Mblk ^= (0u - ((blk >> j) & 1u)) & (c_pm[14 + j] & 0x3FFFu);
    unsigned Ablk = 0;
#pragma unroll
    for (int a = 1; a < 8; a++)
        Ablk ^= ((blk >> a) & 1u) & par(blk & ((c_pm[14 + a] >> 14) & ((1u << a) - 1u)));
    const unsigned T = (unsigned)t;
    unsigned Bt = 0;
#pragma unroll
    for (int a = 1; a < 9; a++)
        Bt ^= ((T >> a) & 1u) & par(T & c_pm[a] & ((1u << a) - 1u));
    const unsigned base_t = Bt ^ par(T & Mblk & 0x1FFu) ^ Ablk;
    const unsigned X9c = par(T & c_pm[9] & 0x1FFu) ^ ((Mblk >> 9) & 1u);
    unsigned km = 0;
#pragma unroll
    for (int b = 0; b < 4; b++)
        km |= (par(T & c_pm[10 + b] & 0x1FFu) ^ ((Mblk >> (10 + b)) & 1u)) << b;
    const unsigned mask9i = (c_pm[9] >> 10) & 15u;
    unsigned ab = 0;
#pragma unroll
    for (int a = 1; a < 4; a++)
        ab ^= (((unsigned)lane >> a) & 1u) &
              par((unsigned)lane & ((c_pm[10 + a] >> 10) & ((1u << a) - 1u)));
    const unsigned Wakk = __ballot_sync(FULL, ab);   // bit i = internal parity of i

    // ---- A: stage SA {4 int, 0-3 packed}
    bflyp<0>(p, c_c[SA][4], c_s[SA][4]);
    bflyp<1>(p, c_c[SA][0], c_s[SA][0]);
    bflyp<2>(p, c_c[SA][1], c_s[SA][1]);
    bflyp<3>(p, c_c[SA][2], c_s[SA][2]);
    bflyp<4>(p, c_c[SA][3], c_s[SA][3]);

#pragma unroll
    for (int j = 0; j < 16; j++)
        *reinterpret_cast<ull*>(&sm[lw2((j << 1) | (t << 5))]) = p[j];
    __syncthreads();

    const int yb = ((t & 15) << 1) | ((t >> 4) << 9);
    // ---- B: stage SA {5-8 packed}
#pragma unroll
    for (int i = 0; i < 16; i++)
        p[i] = *reinterpret_cast<const ull*>(&sm[lw2(yb | (i << 5))]);

    bflyp<1>(p, c_c[SA][5], c_s[SA][5]);
    bflyp<2>(p, c_c[SA][6], c_s[SA][6]);
    bflyp<3>(p, c_c[SA][7], c_s[SA][7]);
    bflyp<4>(p, c_c[SA][8], c_s[SA][8]);

#pragma unroll
    for (int i = 0; i < 16; i++)
        *reinterpret_cast<ull*>(&sm[lw2(yb | (i << 5))]) = p[i];
    __syncthreads();

    // ---- C: stage SA {9 int, 10-13 packed} -> SIGN -> stage SB {9-13}
    const int yc = ((t >> 4) & 1) | ((t & 15) << 1) | (((t >> 5) & 15) << 5);
#pragma unroll
    for (int i = 0; i < 16; i++)
        p[i] = pk2(sm[lw2(yc | ((2 * i) << 9))],
                   sm[lw2(yc | ((2 * i + 1) << 9))]);

    bflyp<0>(p, c_c[SA][9],  c_s[SA][9]);
    bflyp<1>(p, c_c[SA][10], c_s[SA][10]);
    bflyp<2>(p, c_c[SA][11], c_s[SA][11]);
    bflyp<3>(p, c_c[SA][12], c_s[SA][12]);
    bflyp<4>(p, c_c[SA][13], c_s[SA][13]);

#pragma unroll
    for (int i = 0; i < 16; i++) {
        unsigned w = (Wakk >> i) & 1u;
        unsigned lo = base_t ^ par((unsigned)i & km) ^ w;
        unsigned hi = base_t ^ X9c ^ par((unsigned)i & (km ^ mask9i)) ^ w;
        p[i] ^= ((ull)hi << 63) | ((ull)lo << 31);
    }

    bflyp<0>(p, c_c[SB][9],  c_s[SB][9]);
    bflyp<1>(p, c_c[SB][10], c_s[SB][10]);
    bflyp<2>(p, c_c[SB][11], c_s[SB][11]);
    bflyp<3>(p, c_c[SB][12], c_s[SB][12]);
    bflyp<4>(p, c_c[SB][13], c_s[SB][13]);

#pragma unroll
    for (int i = 0; i < 16; i++) {
        float2 v = upk2(p[i]);
        sm[lw2(yc | ((2 * i) << 9))] = v.x;
        sm[lw2(yc | ((2 * i + 1) << 9))] = v.y;
    }
    __syncthreads();

    // ---- B': stage SB {5-8}
#pragma unroll
    for (int i = 0; i < 16; i++)
        p[i] = *reinterpret_cast<const ull*>(&sm[lw2(yb | (i << 5))]);

    bflyp<1>(p, c_c[SB][5], c_s[SB][5]);
    bflyp<2>(p, c_c[SB][6], c_s[SB][6]);
    bflyp<3>(p, c_c[SB][7], c_s[SB][7]);
    bflyp<4>(p, c_c[SB][8], c_s[SB][8]);

#pragma unroll
    for (int i = 0; i < 16; i++)
        *reinterpret_cast<ull*>(&sm[lw2(yb | (i << 5))]) = p[i];
    __syncthreads();

    // ---- A': stage SB {4 int, 0-3}, store natural float4
#pragma unroll
    for (int j = 0; j < 16; j++)
        p[j] = *reinterpret_cast<const ull*>(&sm[lw2((j << 1) | (t << 5))]);

    bflyp<0>(p, c_c[SB][4], c_s[SB][4]);
    bflyp<1>(p, c_c[SB][0], c_s[SB][0]);
    bflyp<2>(p, c_c[SB][1], c_s[SB][1]);
    bflyp<3>(p, c_c[SB][2], c_s[SB][2]);
    bflyp<4>(p, c_c[SB][3], c_s[SB][3]);

    {
        float v[32];
#pragma unroll
        for (int j = 0; j < 16; j++) {
            float2 q = upk2(p[j]);
            v[j] = q.x;
            v[j | 16] = q.y;
        }
        float4* gp = reinterpret_cast<float4*>(&g_state[base + t * 32]);
#pragma unroll
        for (int i = 0; i < 8; i++)
            gp[i] = make_float4(v[4 * i], v[4 * i + 1], v[4 * i + 2], v[4 * i + 3]);
    }
}

// ---------------------------------------------------------------- launch
extern "C" void kernel_launch(void* const* d_in, const int* in_sizes, int n_in,
                              void* d_out, int out_size) {
    const float* feat = (const float*)d_in[0];
    const float* adj = (const float*)d_in[1];
    const float* params = (const float*)d_in[2];
    float* out = (float*)d_out;

    const int SMEM = LOWDIM * (int)sizeof(float);   // 65536
    cudaFuncSetAttribute(k_passL1,       cudaFuncAttributeMaxDynamicSharedMemorySize, SMEM);
    cudaFuncSetAttribute(k_passHH<1, 2>, cudaFuncAttributeMaxDynamicSharedMemorySize, SMEM);
    cudaFuncSetAttribute(k_passLL<2, 3>, cudaFuncAttributeMaxDynamicSharedMemorySize, SMEM);
    cudaFuncSetAttribute(k_passHE<3>,    cudaFuncAttributeMaxDynamicSharedMemorySize, SMEM);

    k_setup<<<1, 128>>>(feat, adj, params, out);

    // stage coefficients into __constant__ (D2D, graph-capturable)
    void *pc = nullptr, *ps = nullptr, *pm = nullptr;
    cudaGetSymbolAddress(&pc, g_ccs);
    cudaGetSymbolAddress(&ps, g_sss);
    cudaGetSymbolAddress(&pm, g_pms);
    cudaMemcpyToSymbolAsync(c_c, pc, sizeof(float) * 4 * NQ, 0, cudaMemcpyDeviceToDevice);
    cudaMemcpyToSymbolAsync(c_s, ps, sizeof(float) * 4 * NQ, 0, cudaMemcpyDeviceToDevice);
    cudaMemcpyToSymbolAsync(c_pm, pm, sizeof(unsigned) * NQ, 0, cudaMemcpyDeviceToDevice);

    k_passL1      <<<DIM / LOWDIM, 512, SMEM>>>();
    k_passHH<1, 2><<<LOWDIM / 64, 512, SMEM>>>();
    k_passLL<2, 3><<<DIM / LOWDIM, 512, SMEM>>>();
    k_passHE<3>   <<<LOWDIM / 64, 512, SMEM>>>(out);
}